// round 10
// baseline (speedup 1.0000x reference)
#include <cuda_runtime.h>
#include <cuda_bf16.h>
#include <math.h>
#include <stdint.h>

#define HIDDEN 2048
#define NHEADS 16
#define HDIM   128
#define BATCH  2
#define SEQ    2048
#define BT     (BATCH*SEQ)   // 4096

// ---------------- scratch (static device arrays: no allocation) ----------------
__device__ float g_q[(size_t)BATCH*NHEADS*SEQ*HDIM];     // [B,H,T,D] fp32
__device__ float g_k[(size_t)BATCH*NHEADS*SEQ*HDIM];
__device__ float g_v[(size_t)BATCH*NHEADS*SEQ*HDIM];
__device__ float g_attn[(size_t)BT*HIDDEN];              // [B,T,C] fp32

__device__ __nv_bfloat16 g_xh[(size_t)BT*HIDDEN],  g_xl[(size_t)BT*HIDDEN];
__device__ __nv_bfloat16 g_ah[(size_t)BT*HIDDEN],  g_al[(size_t)BT*HIDDEN];
__device__ __nv_bfloat16 g_wqh[(size_t)HIDDEN*HIDDEN], g_wql[(size_t)HIDDEN*HIDDEN];
__device__ __nv_bfloat16 g_wkh[(size_t)HIDDEN*HIDDEN], g_wkl[(size_t)HIDDEN*HIDDEN];
__device__ __nv_bfloat16 g_wvh[(size_t)HIDDEN*HIDDEN], g_wvl[(size_t)HIDDEN*HIDDEN];
__device__ __nv_bfloat16 g_woh[(size_t)HIDDEN*HIDDEN], g_wol[(size_t)HIDDEN*HIDDEN];

// ======================= portable PTX helpers (sm_80+ ISA only) =======================
__device__ __forceinline__ uint32_t smem_u32(const void* p) {
    uint32_t a;
    asm("{ .reg .u64 t; cvta.to.shared.u64 t, %1; cvt.u32.u64 %0, t; }"
        : "=r"(a) : "l"(p));
    return a;
}

#define CP_ASYNC16(smaddr, gaddr) \
    asm volatile("cp.async.cg.shared.global [%0], [%1], 16;" \
        :: "r"(smaddr), "l"(gaddr))
#define CP_COMMIT() asm volatile("cp.async.commit_group;" ::: "memory")
#define CP_WAIT0()  asm volatile("cp.async.wait_group 0;"  ::: "memory")

#define LDMATRIX_X4(r0, r1, r2, r3, addr) \
    asm volatile("ldmatrix.sync.aligned.m8n8.x4.shared.b16 {%0,%1,%2,%3}, [%4];" \
        : "=r"(r0), "=r"(r1), "=r"(r2), "=r"(r3) : "r"(addr))

#define MMA_BF16(d, a, b) \
    asm volatile( \
        "mma.sync.aligned.m16n8k16.row.col.f32.bf16.bf16.f32 " \
        "{%0,%1,%2,%3}, {%4,%5,%6,%7}, {%8,%9}, {%0,%1,%2,%3};" \
        : "+f"((d)[0]), "+f"((d)[1]), "+f"((d)[2]), "+f"((d)[3]) \
        : "r"((a)[0]), "r"((a)[1]), "r"((a)[2]), "r"((a)[3]), \
          "r"((b)[0]), "r"((b)[1]))

// =================================================================================
// split fp32 -> bf16 hi + bf16 lo  (a = hi + lo + O(2^-18 a))
// =================================================================================
__global__ void split_bf16(const float* __restrict__ s, __nv_bfloat16* __restrict__ h,
                           __nv_bfloat16* __restrict__ l, int n4)
{
    int i = blockIdx.x * blockDim.x + threadIdx.x;
    if (i >= n4) return;
    float4 a = ((const float4*)s)[i];
    __nv_bfloat16 h0 = __float2bfloat16(a.x), h1 = __float2bfloat16(a.y);
    __nv_bfloat16 h2 = __float2bfloat16(a.z), h3 = __float2bfloat16(a.w);
    __nv_bfloat16 l0 = __float2bfloat16(a.x - __bfloat162float(h0));
    __nv_bfloat16 l1 = __float2bfloat16(a.y - __bfloat162float(h1));
    __nv_bfloat16 l2 = __float2bfloat16(a.z - __bfloat162float(h2));
    __nv_bfloat16 l3 = __float2bfloat16(a.w - __bfloat162float(h3));
    __nv_bfloat162 hv0, hv1, lv0, lv1;
    hv0.x = h0; hv0.y = h1; hv1.x = h2; hv1.y = h3;
    lv0.x = l0; lv0.y = l1; lv1.x = l2; lv1.y = l3;
    ((__nv_bfloat162*)h)[i * 2]     = hv0;
    ((__nv_bfloat162*)h)[i * 2 + 1] = hv1;
    ((__nv_bfloat162*)l)[i * 2]     = lv0;
    ((__nv_bfloat162*)l)[i * 2 + 1] = lv1;
}

// =================================================================================
// HMMA GEMM:  C[M,N] = A[M,K] * B[N,K]^T, bf16x3 emulated fp32 (3 mma per product).
// CTA tile 128x128, 8 warps (4 M x 2 N), warp tile 32x64, K-chunk 32 bf16,
// cp.async double-buffered smem, ldmatrix fragments.
// mode 0: C row-major [M,N]; mode 1: scatter to [B,H,T,D] (col tile 128 == head).
// =================================================================================
#define GPB    80                 // smem row pitch in bytes (32 bf16 data + 8 pad)
#define GTILE  (128 * GPB)        // 10240 B per tile
#define GSTAGE (4 * GTILE)        // Ah, Al, Bh, Bl  = 40960 B
#define GSMEM  (2 * GSTAGE)       // 81920 B

__device__ __forceinline__ void gemm_load_stage(
    uint32_t sbase, int buf,
    const __nv_bfloat16* __restrict__ Ah, const __nv_bfloat16* __restrict__ Al,
    const __nv_bfloat16* __restrict__ Bh, const __nv_bfloat16* __restrict__ Bl,
    int aRow0, int bRow0, int koff, int K, int tid)
{
    const uint32_t sb = sbase + buf * GSTAGE;
    #pragma unroll
    for (int it = 0; it < 2; it++) {
        const int q   = tid + it * 256;      // 0..511
        const int row = q >> 2;              // 0..127
        const int kc  = q & 3;               // 16B chunk in row
        const uint32_t so = row * GPB + kc * 16;
        const size_t ga = (size_t)(aRow0 + row) * K + koff + kc * 8;
        const size_t gb = (size_t)(bRow0 + row) * K + koff + kc * 8;
        CP_ASYNC16(sb + so,             (const void*)(Ah + ga));
        CP_ASYNC16(sb + GTILE + so,     (const void*)(Al + ga));
        CP_ASYNC16(sb + 2 * GTILE + so, (const void*)(Bh + gb));
        CP_ASYNC16(sb + 3 * GTILE + so, (const void*)(Bl + gb));
    }
}

__global__ void __launch_bounds__(256, 1)
gemm_mma(const __nv_bfloat16* __restrict__ Ah, const __nv_bfloat16* __restrict__ Al,
         const __nv_bfloat16* __restrict__ Bh, const __nv_bfloat16* __restrict__ Bl,
         float* __restrict__ C, int K, int N, int mode)
{
    extern __shared__ char sm[];
    const uint32_t sbase = smem_u32(sm);
    const int tid  = threadIdx.x;
    const int wid  = tid >> 5;
    const int lane = tid & 31;
    const int wm   = wid & 3;          // M block (32 rows)
    const int wn   = wid >> 2;         // N block (64 cols)
    const int bn   = blockIdx.x;
    const int bm   = blockIdx.y;
    const int aRow0 = bm * 128;
    const int bRow0 = bn * 128;
    const int NKC   = K >> 5;          // 64 chunks of 32

    float acc[2][8][4];
    #pragma unroll
    for (int mt = 0; mt < 2; mt++)
        #pragma unroll
        for (int nt = 0; nt < 8; nt++)
            #pragma unroll
            for (int e = 0; e < 4; e++) acc[mt][nt][e] = 0.0f;

    // per-lane ldmatrix addressing pieces
    const uint32_t lrow = lane & 15;
    const uint32_t lkh  = (lane >> 4) * 16;   // k-half byte offset within k16

    // preload chunk 0
    gemm_load_stage(sbase, 0, Ah, Al, Bh, Bl, aRow0, bRow0, 0, K, tid);
    CP_COMMIT();
    CP_WAIT0();
    __syncthreads();

    for (int c = 0; c < NKC; c++) {
        const int cur = c & 1;
        if (c + 1 < NKC) {
            gemm_load_stage(sbase, cur ^ 1, Ah, Al, Bh, Bl,
                            aRow0, bRow0, (c + 1) * 32, K, tid);
            CP_COMMIT();
        }

        const uint32_t abase = sbase + cur * GSTAGE;
        const uint32_t bbase = abase + 2 * GTILE;

        #pragma unroll
        for (int kk = 0; kk < 2; kk++) {
            const uint32_t ksel = kk * 32 + lkh;
            uint32_t ah_[2][4], al_[2][4];
            #pragma unroll
            for (int mt = 0; mt < 2; mt++) {
                const uint32_t ra = abase + (wm * 32 + mt * 16 + lrow) * GPB + ksel;
                LDMATRIX_X4(ah_[mt][0], ah_[mt][1], ah_[mt][2], ah_[mt][3], ra);
                LDMATRIX_X4(al_[mt][0], al_[mt][1], al_[mt][2], al_[mt][3], ra + GTILE);
            }
            uint32_t bh_[8][2], bl_[8][2];
            #pragma unroll
            for (int p = 0; p < 4; p++) {
                const uint32_t rb = bbase + (wn * 64 + p * 16 + lrow) * GPB + ksel;
                uint32_t r0, r1, r2, r3;
                LDMATRIX_X4(r0, r1, r2, r3, rb);
                bh_[2*p][0] = r0; bh_[2*p][1] = r2;
                bh_[2*p+1][0] = r1; bh_[2*p+1][1] = r3;
                LDMATRIX_X4(r0, r1, r2, r3, rb + GTILE);
                bl_[2*p][0] = r0; bl_[2*p][1] = r2;
                bl_[2*p+1][0] = r1; bl_[2*p+1][1] = r3;
            }
            #pragma unroll
            for (int mt = 0; mt < 2; mt++)
                #pragma unroll
                for (int nt = 0; nt < 8; nt++) {
                    MMA_BF16(acc[mt][nt], ah_[mt], bh_[nt]);
                    MMA_BF16(acc[mt][nt], ah_[mt], bl_[nt]);
                    MMA_BF16(acc[mt][nt], al_[mt], bh_[nt]);
                }
        }

        if (c + 1 < NKC) {
            CP_WAIT0();
            __syncthreads();
        }
    }

    // ---- epilogue ----
    const int tr = lane >> 2;          // 0..7
    const int tc = (lane & 3) * 2;     // 0,2,4,6
    #pragma unroll
    for (int mt = 0; mt < 2; mt++) {
        #pragma unroll
        for (int rr = 0; rr < 2; rr++) {
            const int m = aRow0 + wm * 32 + mt * 16 + rr * 8 + tr;
            float* dst;
            if (mode == 0) {
                dst = C + (size_t)m * N + bn * 128;
            } else {
                const int bb = m >> 11;
                const int t  = m & 2047;
                dst = C + ((((size_t)(bb * NHEADS + bn)) * SEQ + t) << 7);
            }
            #pragma unroll
            for (int nt = 0; nt < 8; nt++) {
                float2 v;
                v.x = acc[mt][nt][rr * 2 + 0];
                v.y = acc[mt][nt][rr * 2 + 1];
                *(float2*)(dst + wn * 64 + nt * 8 + tc) = v;
            }
        }
    }
}

// =================================================================================
// RoPE (in-place on q and k, layout [B,H,T,D], D=128, pairs (d, d+64))
// =================================================================================
__global__ void rope_kernel(float* __restrict__ q, float* __restrict__ k)
{
    const int idx = blockIdx.x * blockDim.x + threadIdx.x;
    const int i   = idx & 63;
    const int row = idx >> 6;
    const int t   = row & (SEQ - 1);

    const float inv = exp2f(-(float)i * 0.20762050593046014f);  // 10000^(-i/64)
    const float ang = (float)t * inv;
    float s, c;
    sincosf(ang, &s, &c);

    float* qp = q + (size_t)row * HDIM;
    float* kp = k + (size_t)row * HDIM;
    const float q1 = qp[i], q2 = qp[i + 64];
    qp[i]      = q1 * c - q2 * s;
    qp[i + 64] = q2 * c + q1 * s;
    const float k1 = kp[i], k2 = kp[i + 64];
    kp[i]      = k1 * c - k2 * s;
    kp[i + 64] = k2 * c + k1 * s;
}

// =================================================================================
// Flash attention, fp32, causal. BM=BN=64, D=128, 256 threads (2 warps/SMSP).
// =================================================================================
__global__ void __launch_bounds__(256, 1)
flash_attn(const float* __restrict__ q, const float* __restrict__ k,
           const float* __restrict__ v, float* __restrict__ outp)
{
    extern __shared__ float smf[];
    float* Qs = smf;                         // [64][129]
    float* Ks = smf + 64 * 129;              // [64][129]
    float* Vs = smf + 2 * 64 * 129;          // [64][132]
    float* Ps = Vs + 64 * 132;               // [64][65]
    float* row_m     = Ps + 64 * 65;         // [64]
    float* row_l     = row_m + 64;           // [64]
    float* row_alpha = row_l + 64;           // [64]

    const int tid = threadIdx.x;
    const int bh  = blockIdx.y;
    const int qi  = (gridDim.x - 1) - blockIdx.x;   // heavy q-tiles first
    const float scale = 0.08838834764831845f;       // 1/sqrt(128)

    const float* qbase = q + ((size_t)bh * SEQ + (size_t)qi * 64) * HDIM;
    for (int idx = tid; idx < 64 * HDIM / 4; idx += 256) {
        const int r = idx >> 5;
        const int c = (idx & 31) << 2;
        float4 t4 = *(const float4*)(qbase + r * HDIM + c);
        Qs[r * 129 + c + 0] = t4.x * scale;
        Qs[r * 129 + c + 1] = t4.y * scale;
        Qs[r * 129 + c + 2] = t4.z * scale;
        Qs[r * 129 + c + 3] = t4.w * scale;
    }
    if (tid < 64) { row_m[tid] = -1e30f; row_l[tid] = 0.0f; }

    float oacc[32];
    #pragma unroll
    for (int i = 0; i < 32; i++) oacc[i] = 0.0f;

    const int r_own = tid & 63;       // PV: owned row
    const int qtr   = tid >> 6;       // PV: 32-col quarter of D
    const int r0 = (tid >> 3) * 2;    // S micro-tile: 2 rows x 8 cols
    const int c0 = (tid & 7) * 8;

    __syncthreads();

    for (int j = 0; j <= qi; j++) {
        const float* kb = k + ((size_t)bh * SEQ + (size_t)j * 64) * HDIM;
        const float* vb = v + ((size_t)bh * SEQ + (size_t)j * 64) * HDIM;
        for (int idx = tid; idx < 64 * HDIM / 4; idx += 256) {
            const int r = idx >> 5;
            const int c = (idx & 31) << 2;
            float4 kt4 = *(const float4*)(kb + r * HDIM + c);
            Ks[r * 129 + c + 0] = kt4.x; Ks[r * 129 + c + 1] = kt4.y;
            Ks[r * 129 + c + 2] = kt4.z; Ks[r * 129 + c + 3] = kt4.w;
            float4 vt4 = *(const float4*)(vb + r * HDIM + c);
            *(float4*)&Vs[r * 132 + c] = vt4;
        }
        __syncthreads();

        // ---- S = Qs * Ks^T ----
        float sacc[2][8];
        #pragma unroll
        for (int i = 0; i < 2; i++)
            #pragma unroll
            for (int jj = 0; jj < 8; jj++) sacc[i][jj] = 0.0f;

        #pragma unroll 4
        for (int kk = 0; kk < HDIM; kk++) {
            float qf[2], kf[8];
            #pragma unroll
            for (int i = 0; i < 2; i++)  qf[i]  = Qs[(r0 + i) * 129 + kk];
            #pragma unroll
            for (int jj = 0; jj < 8; jj++) kf[jj] = Ks[(c0 + jj) * 129 + kk];
            #pragma unroll
            for (int i = 0; i < 2; i++)
                #pragma unroll
                for (int jj = 0; jj < 8; jj++)
                    sacc[i][jj] = fmaf(qf[i], kf[jj], sacc[i][jj]);
        }

        const bool diag = (j == qi);
        #pragma unroll
        for (int i = 0; i < 2; i++)
            #pragma unroll
            for (int jj = 0; jj < 8; jj++) {
                float sv = sacc[i][jj];
                if (diag && (c0 + jj) > (r0 + i)) sv = -1e30f;
                Ps[(r0 + i) * 65 + (c0 + jj)] = sv;
            }
        __syncthreads();

        // ---- online softmax (one thread per row) ----
        if (tid < 64) {
            const int r = tid;
            const float mold = row_m[r];
            float mx = mold;
            #pragma unroll 8
            for (int c = 0; c < 64; c++) mx = fmaxf(mx, Ps[r * 65 + c]);
            const float alpha = __expf(mold - mx);
            float sum = 0.0f;
            #pragma unroll 8
            for (int c = 0; c < 64; c++) {
                const float p = __expf(Ps[r * 65 + c] - mx);
                Ps[r * 65 + c] = p;
                sum += p;
            }
            row_l[r]     = row_l[r] * alpha + sum;
            row_m[r]     = mx;
            row_alpha[r] = alpha;
        }
        __syncthreads();

        // ---- O = O*alpha + P*V ----
        const float alpha = row_alpha[r_own];
        #pragma unroll
        for (int c = 0; c < 32; c++) oacc[c] *= alpha;

        #pragma unroll 2
        for (int kk = 0; kk < 64; kk++) {
            const float p = Ps[r_own * 65 + kk];
            const float4* vr = (const float4*)(Vs + kk * 132 + qtr * 32);
            #pragma unroll
            for (int c4 = 0; c4 < 8; c4++) {
                float4 vv = vr[c4];
                oacc[c4 * 4 + 0] = fmaf(p, vv.x, oacc[c4 * 4 + 0]);
                oacc[c4 * 4 + 1] = fmaf(p, vv.y, oacc[c4 * 4 + 1]);
                oacc[c4 * 4 + 2] = fmaf(p, vv.z, oacc[c4 * 4 + 2]);
                oacc[c4 * 4 + 3] = fmaf(p, vv.w, oacc[c4 * 4 + 3]);
            }
        }
        __syncthreads();
    }

    // ---- normalize + write to [B,T,C] ----
    const float invl = 1.0f / row_l[r_own];
    const int b = bh >> 4;
    const int h = bh & 15;
    const int t = qi * 64 + r_own;
    float* orow = outp + ((size_t)(b * SEQ + t)) * HIDDEN + h * HDIM + qtr * 32;
    #pragma unroll
    for (int c4 = 0; c4 < 8; c4++) {
        float4 o;
        o.x = oacc[c4 * 4 + 0] * invl;
        o.y = oacc[c4 * 4 + 1] * invl;
        o.z = oacc[c4 * 4 + 2] * invl;
        o.w = oacc[c4 * 4 + 3] * invl;
        *(float4*)(orow + c4 * 4) = o;
    }
}

// =================================================================================
// launch
// =================================================================================
extern "C" void kernel_launch(void* const* d_in, const int* in_sizes, int n_in,
                              void* d_out, int out_size)
{
    (void)in_sizes; (void)n_in; (void)out_size;
    const float* x  = (const float*)d_in[0];
    const float* Wq = (const float*)d_in[1];
    const float* Wk = (const float*)d_in[2];
    const float* Wv = (const float*)d_in[3];
    const float* Wo = (const float*)d_in[4];
    float* out = (float*)d_out;

    float *qp, *kp, *vp, *ap;
    __nv_bfloat16 *xh, *xl, *ah, *al;
    __nv_bfloat16 *wqh, *wql, *wkh, *wkl, *wvh, *wvl, *woh, *wol;
    cudaGetSymbolAddress((void**)&qp, g_q);
    cudaGetSymbolAddress((void**)&kp, g_k);
    cudaGetSymbolAddress((void**)&vp, g_v);
    cudaGetSymbolAddress((void**)&ap, g_attn);
    cudaGetSymbolAddress((void**)&xh, g_xh);  cudaGetSymbolAddress((void**)&xl, g_xl);
    cudaGetSymbolAddress((void**)&ah, g_ah);  cudaGetSymbolAddress((void**)&al, g_al);
    cudaGetSymbolAddress((void**)&wqh, g_wqh); cudaGetSymbolAddress((void**)&wql, g_wql);
    cudaGetSymbolAddress((void**)&wkh, g_wkh); cudaGetSymbolAddress((void**)&wkl, g_wkl);
    cudaGetSymbolAddress((void**)&wvh, g_wvh); cudaGetSymbolAddress((void**)&wvl, g_wvl);
    cudaGetSymbolAddress((void**)&woh, g_woh); cudaGetSymbolAddress((void**)&wol, g_wol);

    cudaFuncSetAttribute(gemm_mma, cudaFuncAttributeMaxDynamicSharedMemorySize, GSMEM);
    const int fa_smem = (2 * 64 * 129 + 64 * 132 + 64 * 65 + 3 * 64) * 4; // 117248
    cudaFuncSetAttribute(flash_attn, cudaFuncAttributeMaxDynamicSharedMemorySize, fa_smem);

    const int nx4 = BT * HIDDEN / 4;        // 2097152
    const int nw4 = HIDDEN * HIDDEN / 4;    // 1048576

    split_bf16<<<nx4 / 256, 256>>>(x,  xh,  xl,  nx4);
    split_bf16<<<nw4 / 256, 256>>>(Wq, wqh, wql, nw4);
    split_bf16<<<nw4 / 256, 256>>>(Wk, wkh, wkl, nw4);
    split_bf16<<<nw4 / 256, 256>>>(Wv, wvh, wvl, nw4);
    split_bf16<<<nw4 / 256, 256>>>(Wo, woh, wol, nw4);

    dim3 gg(HIDDEN / 128, BT / 128);   // (16, 32)
    gemm_mma<<<gg, 256, GSMEM>>>(xh, xl, wqh, wql, qp, HIDDEN, HIDDEN, 1);
    gemm_mma<<<gg, 256, GSMEM>>>(xh, xl, wkh, wkl, kp, HIDDEN, HIDDEN, 1);
    gemm_mma<<<gg, 256, GSMEM>>>(xh, xl, wvh, wvl, vp, HIDDEN, HIDDEN, 1);

    rope_kernel<<<(BATCH * NHEADS * SEQ * 64) / 256, 256>>>(qp, kp);

    flash_attn<<<dim3(SEQ / 64, BATCH * NHEADS), 256, fa_smem>>>(qp, kp, vp, ap);

    split_bf16<<<nx4 / 256, 256>>>(ap, ah, al, nx4);
    gemm_mma<<<gg, 256, GSMEM>>>(ah, al, woh, wol, out, HIDDEN, HIDDEN, 0);
}

// round 11
// speedup vs baseline: 1.0006x; 1.0006x over previous
#include <cuda_runtime.h>
#include <cuda_bf16.h>
#include <math.h>
#include <stdint.h>

#define HIDDEN 2048
#define NHEADS 16
#define HDIM   128
#define BATCH  2
#define SEQ    2048
#define BT     (BATCH*SEQ)   // 4096

// ---------------- scratch (static device arrays: no allocation) ----------------
__device__ float g_q[(size_t)BATCH*NHEADS*SEQ*HDIM];     // [B,H,T,D] fp32
__device__ float g_k[(size_t)BATCH*NHEADS*SEQ*HDIM];
__device__ float g_v[(size_t)BATCH*NHEADS*SEQ*HDIM];
__device__ float g_attn[(size_t)BT*HIDDEN];              // [B,T,C] fp32

__device__ __nv_bfloat16 g_xh[(size_t)BT*HIDDEN],  g_xl[(size_t)BT*HIDDEN];
__device__ __nv_bfloat16 g_ah[(size_t)BT*HIDDEN],  g_al[(size_t)BT*HIDDEN];
__device__ __nv_bfloat16 g_wqh[(size_t)HIDDEN*HIDDEN], g_wql[(size_t)HIDDEN*HIDDEN];
__device__ __nv_bfloat16 g_wkh[(size_t)HIDDEN*HIDDEN], g_wkl[(size_t)HIDDEN*HIDDEN];
__device__ __nv_bfloat16 g_wvh[(size_t)HIDDEN*HIDDEN], g_wvl[(size_t)HIDDEN*HIDDEN];
__device__ __nv_bfloat16 g_woh[(size_t)HIDDEN*HIDDEN], g_wol[(size_t)HIDDEN*HIDDEN];

// ======================= portable PTX helpers (sm_80+ ISA only) =======================
__device__ __forceinline__ uint32_t smem_u32(const void* p) {
    uint32_t a;
    asm("{ .reg .u64 t; cvta.to.shared.u64 t, %1; cvt.u32.u64 %0, t; }"
        : "=r"(a) : "l"(p));
    return a;
}

#define CP_ASYNC16(smaddr, gaddr) \
    asm volatile("cp.async.cg.shared.global [%0], [%1], 16;" \
        :: "r"(smaddr), "l"(gaddr))
#define CP_COMMIT() asm volatile("cp.async.commit_group;" ::: "memory")
#define CP_WAIT0()  asm volatile("cp.async.wait_group 0;"  ::: "memory")

#define LDMATRIX_X4(r0, r1, r2, r3, addr) \
    asm volatile("ldmatrix.sync.aligned.m8n8.x4.shared.b16 {%0,%1,%2,%3}, [%4];" \
        : "=r"(r0), "=r"(r1), "=r"(r2), "=r"(r3) : "r"(addr))

#define MMA_BF16(d, a, b) \
    asm volatile( \
        "mma.sync.aligned.m16n8k16.row.col.f32.bf16.bf16.f32 " \
        "{%0,%1,%2,%3}, {%4,%5,%6,%7}, {%8,%9}, {%0,%1,%2,%3};" \
        : "+f"((d)[0]), "+f"((d)[1]), "+f"((d)[2]), "+f"((d)[3]) \
        : "r"((a)[0]), "r"((a)[1]), "r"((a)[2]), "r"((a)[3]), \
          "r"((b)[0]), "r"((b)[1]))

// =================================================================================
// split fp32 -> bf16 hi + bf16 lo  (a = hi + lo + O(2^-18 a))
// =================================================================================
__global__ void split_bf16(const float* __restrict__ s, __nv_bfloat16* __restrict__ h,
                           __nv_bfloat16* __restrict__ l, int n4)
{
    int i = blockIdx.x * blockDim.x + threadIdx.x;
    if (i >= n4) return;
    float4 a = ((const float4*)s)[i];
    __nv_bfloat16 h0 = __float2bfloat16(a.x), h1 = __float2bfloat16(a.y);
    __nv_bfloat16 h2 = __float2bfloat16(a.z), h3 = __float2bfloat16(a.w);
    __nv_bfloat16 l0 = __float2bfloat16(a.x - __bfloat162float(h0));
    __nv_bfloat16 l1 = __float2bfloat16(a.y - __bfloat162float(h1));
    __nv_bfloat16 l2 = __float2bfloat16(a.z - __bfloat162float(h2));
    __nv_bfloat16 l3 = __float2bfloat16(a.w - __bfloat162float(h3));
    __nv_bfloat162 hv0, hv1, lv0, lv1;
    hv0.x = h0; hv0.y = h1; hv1.x = h2; hv1.y = h3;
    lv0.x = l0; lv0.y = l1; lv1.x = l2; lv1.y = l3;
    ((__nv_bfloat162*)h)[i * 2]     = hv0;
    ((__nv_bfloat162*)h)[i * 2 + 1] = hv1;
    ((__nv_bfloat162*)l)[i * 2]     = lv0;
    ((__nv_bfloat162*)l)[i * 2 + 1] = lv1;
}

// =================================================================================
// HMMA GEMM:  C[M,N] = A[M,K] * B[N,K]^T, bf16x3 emulated fp32 (3 mma per product).
// CTA tile 128x128, 8 warps (4 M x 2 N), warp tile 32x64, K-chunk 32 bf16,
// cp.async double-buffered smem, ldmatrix fragments.
// mode 0: C row-major [M,N]; mode 1: scatter to [B,H,T,D] (col tile 128 == head).
// =================================================================================
#define GPB    80                 // smem row pitch in bytes (32 bf16 data + 8 pad)
#define GTILE  (128 * GPB)        // 10240 B per tile
#define GSTAGE (4 * GTILE)        // Ah, Al, Bh, Bl  = 40960 B
#define GSMEM  (2 * GSTAGE)       // 81920 B

__device__ __forceinline__ void gemm_load_stage(
    uint32_t sbase, int buf,
    const __nv_bfloat16* __restrict__ Ah, const __nv_bfloat16* __restrict__ Al,
    const __nv_bfloat16* __restrict__ Bh, const __nv_bfloat16* __restrict__ Bl,
    int aRow0, int bRow0, int koff, int K, int tid)
{
    const uint32_t sb = sbase + buf * GSTAGE;
    #pragma unroll
    for (int it = 0; it < 2; it++) {
        const int q   = tid + it * 256;      // 0..511
        const int row = q >> 2;              // 0..127
        const int kc  = q & 3;               // 16B chunk in row
        const uint32_t so = row * GPB + kc * 16;
        const size_t ga = (size_t)(aRow0 + row) * K + koff + kc * 8;
        const size_t gb = (size_t)(bRow0 + row) * K + koff + kc * 8;
        CP_ASYNC16(sb + so,             (const void*)(Ah + ga));
        CP_ASYNC16(sb + GTILE + so,     (const void*)(Al + ga));
        CP_ASYNC16(sb + 2 * GTILE + so, (const void*)(Bh + gb));
        CP_ASYNC16(sb + 3 * GTILE + so, (const void*)(Bl + gb));
    }
}

__global__ void __launch_bounds__(256, 1)
gemm_mma(const __nv_bfloat16* __restrict__ Ah, const __nv_bfloat16* __restrict__ Al,
         const __nv_bfloat16* __restrict__ Bh, const __nv_bfloat16* __restrict__ Bl,
         float* __restrict__ C, int K, int N, int mode)
{
    extern __shared__ char sm[];
    const uint32_t sbase = smem_u32(sm);
    const int tid  = threadIdx.x;
    const int wid  = tid >> 5;
    const int lane = tid & 31;
    const int wm   = wid & 3;          // M block (32 rows)
    const int wn   = wid >> 2;         // N block (64 cols)
    const int bn   = blockIdx.x;
    const int bm   = blockIdx.y;
    const int aRow0 = bm * 128;
    const int bRow0 = bn * 128;
    const int NKC   = K >> 5;          // 64 chunks of 32

    float acc[2][8][4];
    #pragma unroll
    for (int mt = 0; mt < 2; mt++)
        #pragma unroll
        for (int nt = 0; nt < 8; nt++)
            #pragma unroll
            for (int e = 0; e < 4; e++) acc[mt][nt][e] = 0.0f;

    // per-lane ldmatrix addressing pieces
    const uint32_t lrow = lane & 15;
    const uint32_t lkh  = (lane >> 4) * 16;   // k-half byte offset within k16

    // preload chunk 0
    gemm_load_stage(sbase, 0, Ah, Al, Bh, Bl, aRow0, bRow0, 0, K, tid);
    CP_COMMIT();
    CP_WAIT0();
    __syncthreads();

    for (int c = 0; c < NKC; c++) {
        const int cur = c & 1;
        if (c + 1 < NKC) {
            gemm_load_stage(sbase, cur ^ 1, Ah, Al, Bh, Bl,
                            aRow0, bRow0, (c + 1) * 32, K, tid);
            CP_COMMIT();
        }

        const uint32_t abase = sbase + cur * GSTAGE;
        const uint32_t bbase = abase + 2 * GTILE;

        #pragma unroll
        for (int kk = 0; kk < 2; kk++) {
            const uint32_t ksel = kk * 32 + lkh;
            uint32_t ah_[2][4], al_[2][4];
            #pragma unroll
            for (int mt = 0; mt < 2; mt++) {
                const uint32_t ra = abase + (wm * 32 + mt * 16 + lrow) * GPB + ksel;
                LDMATRIX_X4(ah_[mt][0], ah_[mt][1], ah_[mt][2], ah_[mt][3], ra);
                LDMATRIX_X4(al_[mt][0], al_[mt][1], al_[mt][2], al_[mt][3], ra + GTILE);
            }
            uint32_t bh_[8][2], bl_[8][2];
            #pragma unroll
            for (int p = 0; p < 4; p++) {
                const uint32_t rb = bbase + (wn * 64 + p * 16 + lrow) * GPB + ksel;
                uint32_t r0, r1, r2, r3;
                LDMATRIX_X4(r0, r1, r2, r3, rb);
                bh_[2*p][0] = r0; bh_[2*p][1] = r2;
                bh_[2*p+1][0] = r1; bh_[2*p+1][1] = r3;
                LDMATRIX_X4(r0, r1, r2, r3, rb + GTILE);
                bl_[2*p][0] = r0; bl_[2*p][1] = r2;
                bl_[2*p+1][0] = r1; bl_[2*p+1][1] = r3;
            }
            #pragma unroll
            for (int mt = 0; mt < 2; mt++)
                #pragma unroll
                for (int nt = 0; nt < 8; nt++) {
                    MMA_BF16(acc[mt][nt], ah_[mt], bh_[nt]);
                    MMA_BF16(acc[mt][nt], ah_[mt], bl_[nt]);
                    MMA_BF16(acc[mt][nt], al_[mt], bh_[nt]);
                }
        }

        if (c + 1 < NKC) {
            CP_WAIT0();
            __syncthreads();
        }
    }

    // ---- epilogue ----
    const int tr = lane >> 2;          // 0..7
    const int tc = (lane & 3) * 2;     // 0,2,4,6
    #pragma unroll
    for (int mt = 0; mt < 2; mt++) {
        #pragma unroll
        for (int rr = 0; rr < 2; rr++) {
            const int m = aRow0 + wm * 32 + mt * 16 + rr * 8 + tr;
            float* dst;
            if (mode == 0) {
                dst = C + (size_t)m * N + bn * 128;
            } else {
                const int bb = m >> 11;
                const int t  = m & 2047;
                dst = C + ((((size_t)(bb * NHEADS + bn)) * SEQ + t) << 7);
            }
            #pragma unroll
            for (int nt = 0; nt < 8; nt++) {
                float2 v;
                v.x = acc[mt][nt][rr * 2 + 0];
                v.y = acc[mt][nt][rr * 2 + 1];
                *(float2*)(dst + wn * 64 + nt * 8 + tc) = v;
            }
        }
    }
}

// =================================================================================
// RoPE (in-place on q and k, layout [B,H,T,D], D=128, pairs (d, d+64))
// =================================================================================
__global__ void rope_kernel(float* __restrict__ q, float* __restrict__ k)
{
    const int idx = blockIdx.x * blockDim.x + threadIdx.x;
    const int i   = idx & 63;
    const int row = idx >> 6;
    const int t   = row & (SEQ - 1);

    const float inv = exp2f(-(float)i * 0.20762050593046014f);  // 10000^(-i/64)
    const float ang = (float)t * inv;
    float s, c;
    sincosf(ang, &s, &c);

    float* qp = q + (size_t)row * HDIM;
    float* kp = k + (size_t)row * HDIM;
    const float q1 = qp[i], q2 = qp[i + 64];
    qp[i]      = q1 * c - q2 * s;
    qp[i + 64] = q2 * c + q1 * s;
    const float k1 = kp[i], k2 = kp[i + 64];
    kp[i]      = k1 * c - k2 * s;
    kp[i + 64] = k2 * c + k1 * s;
}

// =================================================================================
// Flash attention, fp32, causal. BM=BN=64, D=128, 256 threads (2 warps/SMSP).
// =================================================================================
__global__ void __launch_bounds__(256, 1)
flash_attn(const float* __restrict__ q, const float* __restrict__ k,
           const float* __restrict__ v, float* __restrict__ outp)
{
    extern __shared__ float smf[];
    float* Qs = smf;                         // [64][129]
    float* Ks = smf + 64 * 129;              // [64][129]
    float* Vs = smf + 2 * 64 * 129;          // [64][132]
    float* Ps = Vs + 64 * 132;               // [64][65]
    float* row_m     = Ps + 64 * 65;         // [64]
    float* row_l     = row_m + 64;           // [64]
    float* row_alpha = row_l + 64;           // [64]

    const int tid = threadIdx.x;
    const int bh  = blockIdx.y;
    const int qi  = (gridDim.x - 1) - blockIdx.x;   // heavy q-tiles first
    const float scale = 0.08838834764831845f;       // 1/sqrt(128)

    const float* qbase = q + ((size_t)bh * SEQ + (size_t)qi * 64) * HDIM;
    for (int idx = tid; idx < 64 * HDIM / 4; idx += 256) {
        const int r = idx >> 5;
        const int c = (idx & 31) << 2;
        float4 t4 = *(const float4*)(qbase + r * HDIM + c);
        Qs[r * 129 + c + 0] = t4.x * scale;
        Qs[r * 129 + c + 1] = t4.y * scale;
        Qs[r * 129 + c + 2] = t4.z * scale;
        Qs[r * 129 + c + 3] = t4.w * scale;
    }
    if (tid < 64) { row_m[tid] = -1e30f; row_l[tid] = 0.0f; }

    float oacc[32];
    #pragma unroll
    for (int i = 0; i < 32; i++) oacc[i] = 0.0f;

    const int r_own = tid & 63;       // PV: owned row
    const int qtr   = tid >> 6;       // PV: 32-col quarter of D
    const int r0 = (tid >> 3) * 2;    // S micro-tile: 2 rows x 8 cols
    const int c0 = (tid & 7) * 8;

    __syncthreads();

    for (int j = 0; j <= qi; j++) {
        const float* kb = k + ((size_t)bh * SEQ + (size_t)j * 64) * HDIM;
        const float* vb = v + ((size_t)bh * SEQ + (size_t)j * 64) * HDIM;
        for (int idx = tid; idx < 64 * HDIM / 4; idx += 256) {
            const int r = idx >> 5;
            const int c = (idx & 31) << 2;
            float4 kt4 = *(const float4*)(kb + r * HDIM + c);
            Ks[r * 129 + c + 0] = kt4.x; Ks[r * 129 + c + 1] = kt4.y;
            Ks[r * 129 + c + 2] = kt4.z; Ks[r * 129 + c + 3] = kt4.w;
            float4 vt4 = *(const float4*)(vb + r * HDIM + c);
            *(float4*)&Vs[r * 132 + c] = vt4;
        }
        __syncthreads();

        // ---- S = Qs * Ks^T ----
        float sacc[2][8];
        #pragma unroll
        for (int i = 0; i < 2; i++)
            #pragma unroll
            for (int jj = 0; jj < 8; jj++) sacc[i][jj] = 0.0f;

        #pragma unroll 4
        for (int kk = 0; kk < HDIM; kk++) {
            float qf[2], kf[8];
            #pragma unroll
            for (int i = 0; i < 2; i++)  qf[i]  = Qs[(r0 + i) * 129 + kk];
            #pragma unroll
            for (int jj = 0; jj < 8; jj++) kf[jj] = Ks[(c0 + jj) * 129 + kk];
            #pragma unroll
            for (int i = 0; i < 2; i++)
                #pragma unroll
                for (int jj = 0; jj < 8; jj++)
                    sacc[i][jj] = fmaf(qf[i], kf[jj], sacc[i][jj]);
        }

        const bool diag = (j == qi);
        #pragma unroll
        for (int i = 0; i < 2; i++)
            #pragma unroll
            for (int jj = 0; jj < 8; jj++) {
                float sv = sacc[i][jj];
                if (diag && (c0 + jj) > (r0 + i)) sv = -1e30f;
                Ps[(r0 + i) * 65 + (c0 + jj)] = sv;
            }
        __syncthreads();

        // ---- online softmax (one thread per row) ----
        if (tid < 64) {
            const int r = tid;
            const float mold = row_m[r];
            float mx = mold;
            #pragma unroll 8
            for (int c = 0; c < 64; c++) mx = fmaxf(mx, Ps[r * 65 + c]);
            const float alpha = __expf(mold - mx);
            float sum = 0.0f;
            #pragma unroll 8
            for (int c = 0; c < 64; c++) {
                const float p = __expf(Ps[r * 65 + c] - mx);
                Ps[r * 65 + c] = p;
                sum += p;
            }
            row_l[r]     = row_l[r] * alpha + sum;
            row_m[r]     = mx;
            row_alpha[r] = alpha;
        }
        __syncthreads();

        // ---- O = O*alpha + P*V ----
        const float alpha = row_alpha[r_own];
        #pragma unroll
        for (int c = 0; c < 32; c++) oacc[c] *= alpha;

        #pragma unroll 2
        for (int kk = 0; kk < 64; kk++) {
            const float p = Ps[r_own * 65 + kk];
            const float4* vr = (const float4*)(Vs + kk * 132 + qtr * 32);
            #pragma unroll
            for (int c4 = 0; c4 < 8; c4++) {
                float4 vv = vr[c4];
                oacc[c4 * 4 + 0] = fmaf(p, vv.x, oacc[c4 * 4 + 0]);
                oacc[c4 * 4 + 1] = fmaf(p, vv.y, oacc[c4 * 4 + 1]);
                oacc[c4 * 4 + 2] = fmaf(p, vv.z, oacc[c4 * 4 + 2]);
                oacc[c4 * 4 + 3] = fmaf(p, vv.w, oacc[c4 * 4 + 3]);
            }
        }
        __syncthreads();
    }

    // ---- normalize + write to [B,T,C] ----
    const float invl = 1.0f / row_l[r_own];
    const int b = bh >> 4;
    const int h = bh & 15;
    const int t = qi * 64 + r_own;
    float* orow = outp + ((size_t)(b * SEQ + t)) * HIDDEN + h * HDIM + qtr * 32;
    #pragma unroll
    for (int c4 = 0; c4 < 8; c4++) {
        float4 o;
        o.x = oacc[c4 * 4 + 0] * invl;
        o.y = oacc[c4 * 4 + 1] * invl;
        o.z = oacc[c4 * 4 + 2] * invl;
        o.w = oacc[c4 * 4 + 3] * invl;
        *(float4*)(orow + c4 * 4) = o;
    }
}

// =================================================================================
// launch
// =================================================================================
extern "C" void kernel_launch(void* const* d_in, const int* in_sizes, int n_in,
                              void* d_out, int out_size)
{
    (void)in_sizes; (void)n_in; (void)out_size;
    const float* x  = (const float*)d_in[0];
    const float* Wq = (const float*)d_in[1];
    const float* Wk = (const float*)d_in[2];
    const float* Wv = (const float*)d_in[3];
    const float* Wo = (const float*)d_in[4];
    float* out = (float*)d_out;

    float *qp, *kp, *vp, *ap;
    __nv_bfloat16 *xh, *xl, *ah, *al;
    __nv_bfloat16 *wqh, *wql, *wkh, *wkl, *wvh, *wvl, *woh, *wol;
    cudaGetSymbolAddress((void**)&qp, g_q);
    cudaGetSymbolAddress((void**)&kp, g_k);
    cudaGetSymbolAddress((void**)&vp, g_v);
    cudaGetSymbolAddress((void**)&ap, g_attn);
    cudaGetSymbolAddress((void**)&xh, g_xh);  cudaGetSymbolAddress((void**)&xl, g_xl);
    cudaGetSymbolAddress((void**)&ah, g_ah);  cudaGetSymbolAddress((void**)&al, g_al);
    cudaGetSymbolAddress((void**)&wqh, g_wqh); cudaGetSymbolAddress((void**)&wql, g_wql);
    cudaGetSymbolAddress((void**)&wkh, g_wkh); cudaGetSymbolAddress((void**)&wkl, g_wkl);
    cudaGetSymbolAddress((void**)&wvh, g_wvh); cudaGetSymbolAddress((void**)&wvl, g_wvl);
    cudaGetSymbolAddress((void**)&woh, g_woh); cudaGetSymbolAddress((void**)&wol, g_wol);

    cudaFuncSetAttribute(gemm_mma, cudaFuncAttributeMaxDynamicSharedMemorySize, GSMEM);
    const int fa_smem = (2 * 64 * 129 + 64 * 132 + 64 * 65 + 3 * 64) * 4; // 117248
    cudaFuncSetAttribute(flash_attn, cudaFuncAttributeMaxDynamicSharedMemorySize, fa_smem);

    const int nx4 = BT * HIDDEN / 4;        // 2097152
    const int nw4 = HIDDEN * HIDDEN / 4;    // 1048576

    split_bf16<<<nx4 / 256, 256>>>(x,  xh,  xl,  nx4);
    split_bf16<<<nw4 / 256, 256>>>(Wq, wqh, wql, nw4);
    split_bf16<<<nw4 / 256, 256>>>(Wk, wkh, wkl, nw4);
    split_bf16<<<nw4 / 256, 256>>>(Wv, wvh, wvl, nw4);
    split_bf16<<<nw4 / 256, 256>>>(Wo, woh, wol, nw4);

    dim3 gg(HIDDEN / 128, BT / 128);   // (16, 32)
    gemm_mma<<<gg, 256, GSMEM>>>(xh, xl, wqh, wql, qp, HIDDEN, HIDDEN, 1);
    gemm_mma<<<gg, 256, GSMEM>>>(xh, xl, wkh, wkl, kp, HIDDEN, HIDDEN, 1);
    gemm_mma<<<gg, 256, GSMEM>>>(xh, xl, wvh, wvl, vp, HIDDEN, HIDDEN, 1);

    rope_kernel<<<(BATCH * NHEADS * SEQ * 64) / 256, 256>>>(qp, kp);

    flash_attn<<<dim3(SEQ / 64, BATCH * NHEADS), 256, fa_smem>>>(qp, kp, vp, ap);

    split_bf16<<<nx4 / 256, 256>>>(ap, ah, al, nx4);
    gemm_mma<<<gg, 256, GSMEM>>>(ah, al, woh, wol, out, HIDDEN, HIDDEN, 0);
}